// round 3
// baseline (speedup 1.0000x reference)
#include <cuda_runtime.h>
#include <math.h>

// B=4, M=256, T=64; fc1: 512->512, fc_out: 1024->768
#define DOUT 768
#define NBT  256   // B*T

// scratch (no allocs allowed)
__device__ float g_U[512 * DOUT];     // W1 @ W2[:512]
__device__ float g_base[256 * DOUT];  // pos_embed @ W2[512:] + C
__device__ float g_C[DOUT];
__device__ float g_P0[NBT * DOUT];
__device__ float g_P1[NBT * DOUT];
__device__ float g_Q [NBT * DOUT];

// ---------------- C[o] = sum_n b1[n]*W2[n,o] + b2[o] ----------------
__global__ void k_C(const float* __restrict__ b1, const float* __restrict__ W2,
                    const float* __restrict__ b2) {
    int o = blockIdx.x * blockDim.x + threadIdx.x;
    float acc = b2[o];
#pragma unroll 8
    for (int n = 0; n < 512; ++n)
        acc = fmaf(b1[n], W2[n * DOUT + o], acc);
    g_C[o] = acc;
}

// ---------------- fused GEMM: rows 0..511 -> U = W1 @ W2[:512]
//                  rows 512..767 -> base = pos_embed @ W2[512:] + C ----------------
__global__ void k_gemm(const float* __restrict__ W1, const float* __restrict__ pe,
                       const float* __restrict__ W2) {
    __shared__ float As[64][16];
    __shared__ float Bs[16][64];
    const int row0 = blockIdx.y * 64;
    const int col0 = blockIdx.x * 64;

    const float* A;
    int koff;
    float* D;
    bool addC;
    if (row0 < 512) { A = W1 + row0 * 512; koff = 0;   D = g_U    + row0 * DOUT;         addC = false; }
    else            { A = pe + (row0 - 512) * 512; koff = 512; D = g_base + (row0 - 512) * DOUT; addC = true; }

    const int tid = threadIdx.x;
    const int tm = (tid >> 4) * 4;
    const int tn = (tid & 15) * 4;

    float acc[4][4];
#pragma unroll
    for (int i = 0; i < 4; ++i)
#pragma unroll
        for (int j = 0; j < 4; ++j) acc[i][j] = 0.f;

    const int ai = tid >> 2, ak = (tid & 3) * 4;
    const int bk = tid >> 6, bj = tid & 63;

    for (int k0 = 0; k0 < 512; k0 += 16) {
        float4 a4 = *(const float4*)(A + ai * 512 + k0 + ak);
        *(float4*)(&As[ai][ak]) = a4;
#pragma unroll
        for (int r = 0; r < 4; ++r)
            Bs[bk + r * 4][bj] = W2[(koff + k0 + bk + r * 4) * DOUT + col0 + bj];
        __syncthreads();
#pragma unroll
        for (int k = 0; k < 16; ++k) {
            float a0 = As[tm + 0][k], a1 = As[tm + 1][k];
            float a2 = As[tm + 2][k], a3 = As[tm + 3][k];
            float b0 = Bs[k][tn + 0], b1 = Bs[k][tn + 1];
            float b2 = Bs[k][tn + 2], b3 = Bs[k][tn + 3];
            acc[0][0] = fmaf(a0, b0, acc[0][0]); acc[0][1] = fmaf(a0, b1, acc[0][1]);
            acc[0][2] = fmaf(a0, b2, acc[0][2]); acc[0][3] = fmaf(a0, b3, acc[0][3]);
            acc[1][0] = fmaf(a1, b0, acc[1][0]); acc[1][1] = fmaf(a1, b1, acc[1][1]);
            acc[1][2] = fmaf(a1, b2, acc[1][2]); acc[1][3] = fmaf(a1, b3, acc[1][3]);
            acc[2][0] = fmaf(a2, b0, acc[2][0]); acc[2][1] = fmaf(a2, b1, acc[2][1]);
            acc[2][2] = fmaf(a2, b2, acc[2][2]); acc[2][3] = fmaf(a2, b3, acc[2][3]);
            acc[3][0] = fmaf(a3, b0, acc[3][0]); acc[3][1] = fmaf(a3, b1, acc[3][1]);
            acc[3][2] = fmaf(a3, b2, acc[3][2]); acc[3][3] = fmaf(a3, b3, acc[3][3]);
        }
        __syncthreads();
    }
#pragma unroll
    for (int i = 0; i < 4; ++i) {
#pragma unroll
        for (int j = 0; j < 4; ++j) {
            float v = acc[i][j];
            if (addC) v += g_C[col0 + tn + j];
            D[(tm + i) * DOUT + col0 + tn + j] = v;
        }
    }
}

// ---------------- P0/P1/Q per (b,t): reductions over j of vis/coords against U ----------------
#define PG 8
__global__ void k_P(const float* __restrict__ coords, const float* __restrict__ vis) {
    __shared__ float sv[PG][256];
    __shared__ float sx[PG][256];
    __shared__ float sy[PG][256];
    const int grp = blockIdx.x;   // 32 groups of PG bt-pairs
    const int ot  = blockIdx.y;   // 3 o-tiles of 256
    const int tid = threadIdx.x;
    const int o = ot * 256 + tid;

    for (int e = tid; e < PG * 256; e += 256) {
        int g = e >> 8, j = e & 255;
        int bt = grp * PG + g;
        int b = bt >> 6, t = bt & 63;
        int ci = ((b * 256 + j) * 64 + t) * 2;
        float x = coords[ci], y = coords[ci + 1];
        float v = vis[(b * 256 + j) * 64 + t];
        if (isnan(x)) { v = 0.f; x = 0.f; }
        if (isnan(y)) y = 0.f;
        sv[g][j] = v;
        sx[g][j] = v * x;
        sy[g][j] = v * y;
    }
    __syncthreads();

    float p0[PG], p1[PG], qq[PG];
#pragma unroll
    for (int g = 0; g < PG; ++g) { p0[g] = 0.f; p1[g] = 0.f; qq[g] = 0.f; }

#pragma unroll 2
    for (int j = 0; j < 256; ++j) {
        float w0 = g_U[(2 * j)     * DOUT + o];
        float w1 = g_U[(2 * j + 1) * DOUT + o];
#pragma unroll
        for (int g = 0; g < PG; ++g) {
            p0[g] = fmaf(sv[g][j], w0, p0[g]);
            p1[g] = fmaf(sv[g][j], w1, p1[g]);
            qq[g] = fmaf(sx[g][j], w0, fmaf(sy[g][j], w1, qq[g]));
        }
    }
#pragma unroll
    for (int g = 0; g < PG; ++g) {
        int bt = grp * PG + g;
        g_P0[bt * DOUT + o] = p0[g];
        g_P1[bt * DOUT + o] = p1[g];
        g_Q [bt * DOUT + o] = qq[g];
    }
}

// ---------------- out[bt,m,o] = vis_m*(cx_m*P0 + cy_m*P1 - Q) + base[m,o] ----------------
__global__ void k_out(const float* __restrict__ coords, const float* __restrict__ vis,
                      float* __restrict__ out) {
    __shared__ float ss0[64][16];   // vis*cx  [bt_local][m_local]
    __shared__ float ss1[64][16];   // vis*cy
    __shared__ float ss2[64][16];   // vis
    const int mg0 = blockIdx.x * 16;  // 16 m-groups
    const int ot  = blockIdx.y;       // 3 o-tiles (256 each)
    const int btc = blockIdx.z * 64;  // 4 bt-chunks
    const int tid = threadIdx.x;

    for (int e = tid; e < 1024; e += 256) {
        int btl = e >> 4, ml = e & 15;
        int bt = btc + btl;
        int b = bt >> 6, t = bt & 63;
        int m = mg0 + ml;
        int ci = ((b * 256 + m) * 64 + t) * 2;
        float x = coords[ci], y = coords[ci + 1];
        float v = vis[(b * 256 + m) * 64 + t];
        if (isnan(x)) { v = 0.f; x = 0.f; }
        if (isnan(y)) y = 0.f;
        ss0[btl][ml] = v * x;
        ss1[btl][ml] = v * y;
        ss2[btl][ml] = v;
    }
    __syncthreads();

    const int oq  = tid & 63;
    const int mg  = tid >> 6;        // 0..3
    const int o   = ot * 256 + oq * 4;
    const int ml0 = mg * 4;

    float4 base4[4];
#pragma unroll
    for (int r = 0; r < 4; ++r)
        base4[r] = *(const float4*)(g_base + (mg0 + ml0 + r) * DOUT + o);

    for (int btl = 0; btl < 64; ++btl) {
        int bt = btc + btl;
        float4 p0 = *(const float4*)(g_P0 + bt * DOUT + o);
        float4 p1 = *(const float4*)(g_P1 + bt * DOUT + o);
        float4 qv = *(const float4*)(g_Q  + bt * DOUT + o);
#pragma unroll
        for (int r = 0; r < 4; ++r) {
            float a = ss0[btl][ml0 + r];
            float b = ss1[btl][ml0 + r];
            float c = ss2[btl][ml0 + r];
            float4 ov;
            ov.x = fmaf(a, p0.x, fmaf(b, p1.x, fmaf(-c, qv.x, base4[r].x)));
            ov.y = fmaf(a, p0.y, fmaf(b, p1.y, fmaf(-c, qv.y, base4[r].y)));
            ov.z = fmaf(a, p0.z, fmaf(b, p1.z, fmaf(-c, qv.z, base4[r].z)));
            ov.w = fmaf(a, p0.w, fmaf(b, p1.w, fmaf(-c, qv.w, base4[r].w)));
            *(float4*)(out + ((bt * 256 + mg0 + ml0 + r) * DOUT) + o) = ov;
        }
    }
}

extern "C" void kernel_launch(void* const* d_in, const int* in_sizes, int n_in,
                              void* d_out, int out_size) {
    const float* coords = (const float*)d_in[0];  // (4,256,64,2)
    const float* vis    = (const float*)d_in[1];  // (4,256,64)
    const float* pe     = (const float*)d_in[2];  // (256,512)
    const float* W1     = (const float*)d_in[3];  // (512,512)
    const float* b1     = (const float*)d_in[4];  // (512,)
    const float* W2     = (const float*)d_in[5];  // (1024,768)
    const float* b2     = (const float*)d_in[6];  // (768,)
    float* out = (float*)d_out;                   // (4,64,256,768)

    k_C   <<<3, 256>>>(b1, W2, b2);
    k_gemm<<<dim3(12, 12), 256>>>(W1, pe, W2);
    k_P   <<<dim3(32, 3),  256>>>(coords, vis);
    k_out <<<dim3(16, 3, 4), 256>>>(coords, vis, out);
}

// round 4
// speedup vs baseline: 1.7976x; 1.7976x over previous
#include <cuda_runtime.h>
#include <math.h>

// B=4, M=256, T=64; fc1: 512->512, fc_out: 1024->768
#define DOUT 768
#define NBT  256   // B*T

// scratch (no allocs allowed)
__device__ float g_U2[512 * DOUT];    // interleaved: [j][o][d] = (W1@W2[:512])[2j+d, o]
__device__ float g_base[256 * DOUT];  // pos_embed @ W2[512:]  (C added later)
__device__ float g_C[DOUT];           // b1 @ W2[:512] + b2
__device__ float g_P0[NBT * DOUT];
__device__ float g_P1[NBT * DOUT];
__device__ float g_Q [NBT * DOUT];

// ---------------- fused GEMM ----------------
// grid (12, 25):
//   y in [0,16):  U rows (32 per block) = W1 @ W2[:512], stored interleaved into g_U2
//   y in [16,24): base rows (32 per block) = pos_embed @ W2[512:]
//   y == 24:      C[col0..col0+63] = b1 @ W2[:512] + b2
__global__ void k_gemm(const float* __restrict__ W1, const float* __restrict__ pe,
                       const float* __restrict__ W2,
                       const float* __restrict__ b1, const float* __restrict__ b2) {
    const int col0 = blockIdx.x * 64;
    const int tid = threadIdx.x;

    if (blockIdx.y == 24) {
        // C reduction: 64 cols, 4 partial sums per col
        __shared__ float red[4][64];
        const int col = tid & 63;
        const int sub = tid >> 6;          // 0..3, each covers 128 n
        float acc = 0.f;
        const int n0 = sub * 128;
#pragma unroll 4
        for (int i = 0; i < 128; ++i)
            acc = fmaf(b1[n0 + i], W2[(n0 + i) * DOUT + col0 + col], acc);
        red[sub][col] = acc;
        __syncthreads();
        if (sub == 0)
            g_C[col0 + col] = red[0][col] + red[1][col] + red[2][col] + red[3][col] + b2[col0 + col];
        return;
    }

    __shared__ float As[32][16];
    __shared__ float Bs[16][64];
    const int row0 = blockIdx.y * 32;
    const bool isU = (row0 < 512);
    const float* A = isU ? (W1 + row0 * 512) : (pe + (row0 - 512) * 512);
    const int koff = isU ? 0 : 512;

    const int tm = (tid >> 4) * 2;     // 0..30
    const int tn = (tid & 15) * 4;     // 0..60

    float acc[2][4];
#pragma unroll
    for (int i = 0; i < 2; ++i)
#pragma unroll
        for (int j = 0; j < 4; ++j) acc[i][j] = 0.f;

    const int ai = tid >> 3, ak = (tid & 7) * 2;   // 32x16 A tile, float2 each
    const int bk = tid >> 6, bj = tid & 63;        // 16x64 B tile, 4 rows each

    for (int k0 = 0; k0 < 512; k0 += 16) {
        float2 a2 = *(const float2*)(A + ai * 512 + k0 + ak);
        *(float2*)(&As[ai][ak]) = a2;
#pragma unroll
        for (int r = 0; r < 4; ++r)
            Bs[bk + r * 4][bj] = W2[(koff + k0 + bk + r * 4) * DOUT + col0 + bj];
        __syncthreads();
#pragma unroll
        for (int k = 0; k < 16; ++k) {
            float a0 = As[tm + 0][k], a1 = As[tm + 1][k];
            float b0 = Bs[k][tn + 0], b1v = Bs[k][tn + 1];
            float b2v = Bs[k][tn + 2], b3 = Bs[k][tn + 3];
            acc[0][0] = fmaf(a0, b0, acc[0][0]); acc[0][1] = fmaf(a0, b1v, acc[0][1]);
            acc[0][2] = fmaf(a0, b2v, acc[0][2]); acc[0][3] = fmaf(a0, b3, acc[0][3]);
            acc[1][0] = fmaf(a1, b0, acc[1][0]); acc[1][1] = fmaf(a1, b1v, acc[1][1]);
            acc[1][2] = fmaf(a1, b2v, acc[1][2]); acc[1][3] = fmaf(a1, b3, acc[1][3]);
        }
        __syncthreads();
    }

    if (isU) {
        // interleaved store: g_U2[(j*DOUT + o)*2 + d], gr = 2j+d
#pragma unroll
        for (int i = 0; i < 2; ++i) {
            int gr = row0 + tm + i;
            int j = gr >> 1, d = gr & 1;
#pragma unroll
            for (int c = 0; c < 4; ++c)
                g_U2[(j * DOUT + col0 + tn + c) * 2 + d] = acc[i][c];
        }
    } else {
#pragma unroll
        for (int i = 0; i < 2; ++i) {
            float4 v = make_float4(acc[i][0], acc[i][1], acc[i][2], acc[i][3]);
            *(float4*)(g_base + (row0 - 512 + tm + i) * DOUT + col0 + tn) = v;
        }
    }
}

// ---------------- P0/P1/Q per (b,t) ----------------
#define PG 4
__global__ void k_P(const float* __restrict__ coords, const float* __restrict__ vis) {
    __shared__ float sv[PG][256];
    __shared__ float sx[PG][256];
    __shared__ float sy[PG][256];
    const int grp = blockIdx.x;   // 64 groups of PG bt
    const int ot  = blockIdx.y;   // 3 o-tiles of 256
    const int tid = threadIdx.x;
    const int o = ot * 256 + tid;

    for (int e = tid; e < PG * 256; e += 256) {
        int g = e >> 8, j = e & 255;
        int bt = grp * PG + g;
        int b = bt >> 6, t = bt & 63;
        int ci = ((b * 256 + j) * 64 + t) * 2;
        float x = coords[ci], y = coords[ci + 1];
        float v = vis[(b * 256 + j) * 64 + t];
        if (isnan(x)) { v = 0.f; x = 0.f; }
        if (isnan(y)) y = 0.f;
        sv[g][j] = v;
        sx[g][j] = v * x;
        sy[g][j] = v * y;
    }
    __syncthreads();

    float p0[PG], p1[PG], qq[PG];
#pragma unroll
    for (int g = 0; g < PG; ++g) { p0[g] = 0.f; p1[g] = 0.f; qq[g] = 0.f; }

#pragma unroll 4
    for (int j = 0; j < 256; ++j) {
        float2 u = *(const float2*)(g_U2 + (j * DOUT + o) * 2);
#pragma unroll
        for (int g = 0; g < PG; ++g) {
            p0[g] = fmaf(sv[g][j], u.x, p0[g]);
            p1[g] = fmaf(sv[g][j], u.y, p1[g]);
            qq[g] = fmaf(sx[g][j], u.x, fmaf(sy[g][j], u.y, qq[g]));
        }
    }
#pragma unroll
    for (int g = 0; g < PG; ++g) {
        int bt = grp * PG + g;
        g_P0[bt * DOUT + o] = p0[g];
        g_P1[bt * DOUT + o] = p1[g];
        g_Q [bt * DOUT + o] = qq[g];
    }
}

// ---------------- out[bt,m,o] = vis_m*(cx_m*P0 + cy_m*P1 - Q) + base[m,o] + C[o] ----------------
__global__ void k_out(const float* __restrict__ coords, const float* __restrict__ vis,
                      float* __restrict__ out) {
    __shared__ float ss0[16][16];   // vis*cx [bt_local][m_local]
    __shared__ float ss1[16][16];   // vis*cy
    __shared__ float ss2[16][16];   // vis
    const int mg0 = blockIdx.x * 16;  // 16 m-groups
    const int ot  = blockIdx.y;       // 3 o-tiles (256 each)
    const int btc = blockIdx.z * 16;  // 16 bt-chunks
    const int tid = threadIdx.x;

    {
        int btl = tid >> 4, ml = tid & 15;
        int bt = btc + btl;
        int b = bt >> 6, t = bt & 63;
        int m = mg0 + ml;
        int ci = ((b * 256 + m) * 64 + t) * 2;
        float x = coords[ci], y = coords[ci + 1];
        float v = vis[(b * 256 + m) * 64 + t];
        if (isnan(x)) { v = 0.f; x = 0.f; }
        if (isnan(y)) y = 0.f;
        ss0[btl][ml] = v * x;
        ss1[btl][ml] = v * y;
        ss2[btl][ml] = v;
    }
    __syncthreads();

    const int oq  = tid & 63;
    const int mg  = tid >> 6;        // 0..3
    const int o   = ot * 256 + oq * 4;
    const int ml0 = mg * 4;

    float4 c4 = *(const float4*)(g_C + o);
    float4 base4[4];
#pragma unroll
    for (int r = 0; r < 4; ++r) {
        float4 bv = *(const float4*)(g_base + (mg0 + ml0 + r) * DOUT + o);
        base4[r].x = bv.x + c4.x; base4[r].y = bv.y + c4.y;
        base4[r].z = bv.z + c4.z; base4[r].w = bv.w + c4.w;
    }

#pragma unroll 2
    for (int btl = 0; btl < 16; ++btl) {
        int bt = btc + btl;
        float4 p0 = *(const float4*)(g_P0 + bt * DOUT + o);
        float4 p1 = *(const float4*)(g_P1 + bt * DOUT + o);
        float4 qv = *(const float4*)(g_Q  + bt * DOUT + o);
#pragma unroll
        for (int r = 0; r < 4; ++r) {
            float a = ss0[btl][ml0 + r];
            float b = ss1[btl][ml0 + r];
            float c = ss2[btl][ml0 + r];
            float4 ov;
            ov.x = fmaf(a, p0.x, fmaf(b, p1.x, fmaf(-c, qv.x, base4[r].x)));
            ov.y = fmaf(a, p0.y, fmaf(b, p1.y, fmaf(-c, qv.y, base4[r].y)));
            ov.z = fmaf(a, p0.z, fmaf(b, p1.z, fmaf(-c, qv.z, base4[r].z)));
            ov.w = fmaf(a, p0.w, fmaf(b, p1.w, fmaf(-c, qv.w, base4[r].w)));
            __stcs((float4*)(out + ((bt * 256 + mg0 + ml0 + r) * DOUT) + o), ov);
        }
    }
}

extern "C" void kernel_launch(void* const* d_in, const int* in_sizes, int n_in,
                              void* d_out, int out_size) {
    const float* coords = (const float*)d_in[0];  // (4,256,64,2)
    const float* vis    = (const float*)d_in[1];  // (4,256,64)
    const float* pe     = (const float*)d_in[2];  // (256,512)
    const float* W1     = (const float*)d_in[3];  // (512,512)
    const float* b1     = (const float*)d_in[4];  // (512,)
    const float* W2     = (const float*)d_in[5];  // (1024,768)
    const float* b2     = (const float*)d_in[6];  // (768,)
    float* out = (float*)d_out;                   // (4,64,256,768)

    k_gemm<<<dim3(12, 25), 256>>>(W1, pe, W2, b1, b2);
    k_P   <<<dim3(64, 3),  256>>>(coords, vis);
    k_out <<<dim3(16, 3, 16), 256>>>(coords, vis, out);
}

// round 8
// speedup vs baseline: 2.0470x; 1.1387x over previous
#include <cuda_runtime.h>
#include <math.h>

// B=4, M=256, T=64; fc1: 512->512, fc_out: 1024->768
#define DOUT 768
#define NBT  256   // B*T

__device__ float g_U2[512 * DOUT];    // interleaved: [(j*DOUT+o)*2+d] = (W1@W2[:512])[2j+d, o]
__device__ float g_base[256 * DOUT];  // pos_embed @ W2[512:]
__device__ float g_C[DOUT];           // b1 @ W2[:512] + b2
__device__ float g_P0[NBT * DOUT];
__device__ float g_P1[NBT * DOUT];
__device__ float g_Q [NBT * DOUT];

// ---------------- fused GEMM ----------------
// grid (12, 13):
//   y in [0,8):  U rows (64/block) = W1 @ W2[:512] -> g_U2 (interleaved)
//   y in [8,12): base rows (64/block) = pos_embed @ W2[512:]
//   y == 12:     C[col0..col0+63] = b1 @ W2[:512] + b2
__global__ void __launch_bounds__(256) k_gemm(
        const float* __restrict__ W1, const float* __restrict__ pe,
        const float* __restrict__ W2,
        const float* __restrict__ b1, const float* __restrict__ b2) {
    const int col0 = blockIdx.x * 64;
    const int tid = threadIdx.x;

    if (blockIdx.y == 12) {
        __shared__ float red[4][64];
        const int col = tid & 63;
        const int sub = tid >> 6;
        float acc = 0.f;
        const int n0 = sub * 128;
#pragma unroll 4
        for (int i = 0; i < 128; ++i)
            acc = fmaf(b1[n0 + i], W2[(n0 + i) * DOUT + col0 + col], acc);
        red[sub][col] = acc;
        __syncthreads();
        if (sub == 0)
            g_C[col0 + col] = red[0][col] + red[1][col] + red[2][col] + red[3][col] + b2[col0 + col];
        return;
    }

    __shared__ float As[16][68];   // transposed A tile: As[k][m], padded
    __shared__ float Bs[16][64];   // Bs[k][n]
    const int row0 = blockIdx.y * 64;
    const bool isU = (row0 < 512);
    const float* A = isU ? (W1 + row0 * 512) : (pe + (row0 - 512) * 512);
    const int koff = isU ? 0 : 512;

    const int tm = (tid >> 4) * 4;     // 0..60 (m within tile)
    const int tn = (tid & 15) * 4;     // 0..60 (n within tile)

    const int ar = tid >> 2;           // 0..63 A row
    const int ac = (tid & 3) * 4;      // 0,4,8,12 A k-offset
    const int bk = tid >> 6;           // 0..3
    const int bj = tid & 63;           // 0..63

    float acc[4][4];
#pragma unroll
    for (int i = 0; i < 4; ++i)
#pragma unroll
        for (int j = 0; j < 4; ++j) acc[i][j] = 0.f;

    // prefetch first tiles into registers
    float4 a4 = *(const float4*)(A + ar * 512 + ac);
    float  b4[4];
#pragma unroll
    for (int r = 0; r < 4; ++r)
        b4[r] = W2[(koff + bk + r * 4) * DOUT + col0 + bj];

    for (int k0 = 0; k0 < 512; k0 += 16) {
        As[ac + 0][ar] = a4.x;
        As[ac + 1][ar] = a4.y;
        As[ac + 2][ar] = a4.z;
        As[ac + 3][ar] = a4.w;
#pragma unroll
        for (int r = 0; r < 4; ++r)
            Bs[bk + r * 4][bj] = b4[r];
        __syncthreads();

        if (k0 + 16 < 512) {
            a4 = *(const float4*)(A + ar * 512 + k0 + 16 + ac);
#pragma unroll
            for (int r = 0; r < 4; ++r)
                b4[r] = W2[(koff + k0 + 16 + bk + r * 4) * DOUT + col0 + bj];
        }

#pragma unroll
        for (int k = 0; k < 16; ++k) {
            float4 av = *(const float4*)(&As[k][tm]);
            float4 bv = *(const float4*)(&Bs[k][tn]);
            acc[0][0] = fmaf(av.x, bv.x, acc[0][0]); acc[0][1] = fmaf(av.x, bv.y, acc[0][1]);
            acc[0][2] = fmaf(av.x, bv.z, acc[0][2]); acc[0][3] = fmaf(av.x, bv.w, acc[0][3]);
            acc[1][0] = fmaf(av.y, bv.x, acc[1][0]); acc[1][1] = fmaf(av.y, bv.y, acc[1][1]);
            acc[1][2] = fmaf(av.y, bv.z, acc[1][2]); acc[1][3] = fmaf(av.y, bv.w, acc[1][3]);
            acc[2][0] = fmaf(av.z, bv.x, acc[2][0]); acc[2][1] = fmaf(av.z, bv.y, acc[2][1]);
            acc[2][2] = fmaf(av.z, bv.z, acc[2][2]); acc[2][3] = fmaf(av.z, bv.w, acc[2][3]);
            acc[3][0] = fmaf(av.w, bv.x, acc[3][0]); acc[3][1] = fmaf(av.w, bv.y, acc[3][1]);
            acc[3][2] = fmaf(av.w, bv.z, acc[3][2]); acc[3][3] = fmaf(av.w, bv.w, acc[3][3]);
        }
        __syncthreads();
    }

    if (isU) {
#pragma unroll
        for (int i = 0; i < 4; ++i) {
            int gr = row0 + tm + i;
            int j = gr >> 1, d = gr & 1;
#pragma unroll
            for (int c = 0; c < 4; ++c)
                g_U2[(j * DOUT + col0 + tn + c) * 2 + d] = acc[i][c];
        }
    } else {
#pragma unroll
        for (int i = 0; i < 4; ++i) {
            float4 v = make_float4(acc[i][0], acc[i][1], acc[i][2], acc[i][3]);
            *(float4*)(g_base + (row0 - 512 + tm + i) * DOUT + col0 + tn) = v;
        }
    }
}

// ---------------- P0/P1/Q per (b,t) ----------------
#define PG 4
__global__ void __launch_bounds__(256) k_P(const float* __restrict__ coords,
                                           const float* __restrict__ vis) {
    __shared__ float  sv [PG][256];
    __shared__ float2 sxy[PG][256];
    const int grp = blockIdx.x;   // 64 groups of PG bt
    const int ot  = blockIdx.y;   // 3 o-tiles of 256
    const int tid = threadIdx.x;
    const int o = ot * 256 + tid;

    for (int e = tid; e < PG * 256; e += 256) {
        int g = e >> 8, j = e & 255;
        int bt = grp * PG + g;
        int b = bt >> 6, t = bt & 63;
        int ci = ((b * 256 + j) * 64 + t) * 2;
        float x = coords[ci], y = coords[ci + 1];
        float v = vis[(b * 256 + j) * 64 + t];
        if (isnan(x)) { v = 0.f; x = 0.f; }
        if (isnan(y)) y = 0.f;
        sv[g][j]  = v;
        sxy[g][j] = make_float2(v * x, v * y);
    }
    __syncthreads();

    float p0[PG], p1[PG], qq[PG];
#pragma unroll
    for (int g = 0; g < PG; ++g) { p0[g] = 0.f; p1[g] = 0.f; qq[g] = 0.f; }

#pragma unroll 8
    for (int j = 0; j < 256; ++j) {
        float2 u = *(const float2*)(g_U2 + (j * DOUT + o) * 2);
#pragma unroll
        for (int g = 0; g < PG; ++g) {
            float2 xy = sxy[g][j];
            p0[g] = fmaf(sv[g][j], u.x, p0[g]);
            p1[g] = fmaf(sv[g][j], u.y, p1[g]);
            qq[g] = fmaf(xy.x, u.x, fmaf(xy.y, u.y, qq[g]));
        }
    }
#pragma unroll
    for (int g = 0; g < PG; ++g) {
        int bt = grp * PG + g;
        g_P0[bt * DOUT + o] = p0[g];
        g_P1[bt * DOUT + o] = p1[g];
        g_Q [bt * DOUT + o] = qq[g];
    }
}

// ---------------- out[bt,m,o] = vis_m*(cx_m*P0 + cy_m*P1 - Q) + base[m,o] + C[o] ----------------
__global__ void __launch_bounds__(256) k_out(const float* __restrict__ coords,
                                             const float* __restrict__ vis,
                                             float* __restrict__ out) {
    __shared__ float ss0[8][16];   // vis*cx [bt_local][m_local]
    __shared__ float ss1[8][16];   // vis*cy
    __shared__ float ss2[8][16];   // vis
    const int mg0 = blockIdx.x * 16;  // 16 m-groups
    const int ot  = blockIdx.y;       // 3 o-tiles (256 each)
    const int btc = blockIdx.z * 8;   // 32 bt-chunks of 8
    const int tid = threadIdx.x;

    if (tid < 128) {
        int btl = tid >> 4, ml = tid & 15;
        int bt = btc + btl;
        int b = bt >> 6, t = bt & 63;
        int m = mg0 + ml;
        int ci = ((b * 256 + m) * 64 + t) * 2;
        float x = coords[ci], y = coords[ci + 1];
        float v = vis[(b * 256 + m) * 64 + t];
        if (isnan(x)) { v = 0.f; x = 0.f; }
        if (isnan(y)) y = 0.f;
        ss0[btl][ml] = v * x;
        ss1[btl][ml] = v * y;
        ss2[btl][ml] = v;
    }
    __syncthreads();

    const int oq  = tid & 63;
    const int mg  = tid >> 6;        // 0..3
    const int o   = ot * 256 + oq * 4;
    const int ml0 = mg * 4;

    float4 c4 = *(const float4*)(g_C + o);
    float4 base4[4];
#pragma unroll
    for (int r = 0; r < 4; ++r) {
        float4 bv = *(const float4*)(g_base + (mg0 + ml0 + r) * DOUT + o);
        base4[r].x = bv.x + c4.x; base4[r].y = bv.y + c4.y;
        base4[r].z = bv.z + c4.z; base4[r].w = bv.w + c4.w;
    }

#pragma unroll
    for (int btl = 0; btl < 8; ++btl) {
        int bt = btc + btl;
        float4 p0 = *(const float4*)(g_P0 + bt * DOUT + o);
        float4 p1 = *(const float4*)(g_P1 + bt * DOUT + o);
        float4 qv = *(const float4*)(g_Q  + bt * DOUT + o);
#pragma unroll
        for (int r = 0; r < 4; ++r) {
            float a = ss0[btl][ml0 + r];
            float b = ss1[btl][ml0 + r];
            float c = ss2[btl][ml0 + r];
            float4 ov;
            ov.x = fmaf(a, p0.x, fmaf(b, p1.x, fmaf(-c, qv.x, base4[r].x)));
            ov.y = fmaf(a, p0.y, fmaf(b, p1.y, fmaf(-c, qv.y, base4[r].y)));
            ov.z = fmaf(a, p0.z, fmaf(b, p1.z, fmaf(-c, qv.z, base4[r].z)));
            ov.w = fmaf(a, p0.w, fmaf(b, p1.w, fmaf(-c, qv.w, base4[r].w)));
            __stcs((float4*)(out + ((bt * 256 + mg0 + ml0 + r) * DOUT) + o), ov);
        }
    }
}

extern "C" void kernel_launch(void* const* d_in, const int* in_sizes, int n_in,
                              void* d_out, int out_size) {
    const float* coords = (const float*)d_in[0];  // (4,256,64,2)
    const float* vis    = (const float*)d_in[1];  // (4,256,64)
    const float* pe     = (const float*)d_in[2];  // (256,512)
    const float* W1     = (const float*)d_in[3];  // (512,512)
    const float* b1     = (const float*)d_in[4];  // (512,)
    const float* W2     = (const float*)d_in[5];  // (1024,768)
    const float* b2     = (const float*)d_in[6];  // (768,)
    float* out = (float*)d_out;                   // (4,64,256,768)

    k_gemm<<<dim3(12, 13), 256>>>(W1, pe, W2, b1, b2);
    k_P   <<<dim3(64, 3),  256>>>(coords, vis);
    k_out <<<dim3(16, 3, 32), 256>>>(coords, vis, out);
}